// round 2
// baseline (speedup 1.0000x reference)
#include <cuda_runtime.h>

#define NN 100000
#define NE 1600000
#define F 128

// -------- scratch (static device globals; no allocations allowed) ----------
__device__ float g_dinv[NN];                 // deg -> deg^-1/2
__device__ float g_enorm[NE];                // per-edge normalization
__device__ float g_h[(size_t)NN * F];        // h = act(x) @ W
__device__ float g_buf[(size_t)NN * F];      // layer output (agg + self + b)
__device__ float g_hf[NN];                   // final-layer per-node scalar

// ---------------------------- normalization --------------------------------
__global__ void k_deg_init() {
    int i = blockIdx.x * blockDim.x + threadIdx.x;
    if (i < NN) g_dinv[i] = 1.0f;            // implicit self-loop weight 1
}

__global__ void k_deg_acc(const int* __restrict__ ei,
                          const float* __restrict__ ew) {
    int e = blockIdx.x * blockDim.x + threadIdx.x;
    if (e < NE) atomicAdd(&g_dinv[ei[NE + e]], ew[e]);
}

__global__ void k_dinv() {
    int i = blockIdx.x * blockDim.x + threadIdx.x;
    if (i < NN) g_dinv[i] = rsqrtf(g_dinv[i]);   // deg >= 1 always
}

__global__ void k_enorm(const int* __restrict__ ei,
                        const float* __restrict__ ew) {
    int e = blockIdx.x * blockDim.x + threadIdx.x;
    if (e < NE) {
        int s = ei[e], d = ei[NE + e];
        g_enorm[e] = g_dinv[s] * ew[e] * g_dinv[d];
    }
}

// ------------------------------- GEMM ---------------------------------------
// g_h[NN,128] = act(A) @ W, act = relu if relu_in. A = (use_gbuf ? g_buf : Aext)
__global__ __launch_bounds__(256) void k_gemm(const float* __restrict__ Aext,
                                              const float* __restrict__ W,
                                              int use_gbuf, int relu_in) {
    const float* __restrict__ A = use_gbuf ? (const float*)g_buf : Aext;
    __shared__ float As[64][32];
    __shared__ float Ws[32][128];
    int tid = threadIdx.x;
    int tx = tid & 31;          // 32 column-groups of 4 cols
    int ty = tid >> 5;          // 8 row-groups of 8 rows
    int row0 = blockIdx.x * 64;
    float acc[8][4] = {};

    for (int kc = 0; kc < F; kc += 32) {
        // load A tile 64x32 (512 float4, 2/thread)
        #pragma unroll
        for (int i = 0; i < 2; i++) {
            int idx = tid + i * 256;
            int r = idx >> 3, c4 = idx & 7;
            int row = row0 + r;
            float4 v = make_float4(0.f, 0.f, 0.f, 0.f);
            if (row < NN) v = *(const float4*)&A[(size_t)row * F + kc + c4 * 4];
            if (relu_in) {
                v.x = fmaxf(v.x, 0.f); v.y = fmaxf(v.y, 0.f);
                v.z = fmaxf(v.z, 0.f); v.w = fmaxf(v.w, 0.f);
            }
            *(float4*)&As[r][c4 * 4] = v;
        }
        // load W tile 32x128 (1024 float4, 4/thread)
        #pragma unroll
        for (int i = 0; i < 4; i++) {
            int idx = tid + i * 256;
            int k = idx >> 5, c4 = idx & 31;
            *(float4*)&Ws[k][c4 * 4] = *(const float4*)&W[(kc + k) * F + c4 * 4];
        }
        __syncthreads();
        #pragma unroll 8
        for (int k = 0; k < 32; k++) {
            float4 w4 = *(const float4*)&Ws[k][tx * 4];
            #pragma unroll
            for (int r = 0; r < 8; r++) {
                float a = As[ty * 8 + r][k];
                acc[r][0] += a * w4.x; acc[r][1] += a * w4.y;
                acc[r][2] += a * w4.z; acc[r][3] += a * w4.w;
            }
        }
        __syncthreads();
    }
    #pragma unroll
    for (int r = 0; r < 8; r++) {
        int row = row0 + ty * 8 + r;
        if (row < NN)
            *(float4*)&g_h[(size_t)row * F + tx * 4] =
                make_float4(acc[r][0], acc[r][1], acc[r][2], acc[r][3]);
    }
}

// out = self_norm * h + b  (initializes g_buf before the edge scatter)
__global__ void k_init(const float* __restrict__ b) {
    int node = blockIdx.x, f = threadIdx.x;
    float dv = g_dinv[node];
    size_t idx = (size_t)node * F + f;
    g_buf[idx] = dv * dv * g_h[idx] + b[f];
}

// scatter: one warp per edge, 4 floats per lane
__global__ void k_scatter(const int* __restrict__ ei) {
    int t = blockIdx.x * blockDim.x + threadIdx.x;
    int e = t >> 5, lane = t & 31;
    if (e >= NE) return;
    int s = ei[e], d = ei[NE + e];
    float w = g_enorm[e];
    float4 v = *(const float4*)&g_h[(size_t)s * F + lane * 4];
    float* o = &g_buf[(size_t)d * F + lane * 4];
    atomicAdd(o + 0, w * v.x);
    atomicAdd(o + 1, w * v.y);
    atomicAdd(o + 2, w * v.z);
    atomicAdd(o + 3, w * v.w);
}

// ------------------------------ final layer --------------------------------
// g_hf[i] = relu(g_buf[i,:]) . W_fin   (warp per node)
__global__ void k_dot(const float* __restrict__ Wf) {
    int t = blockIdx.x * blockDim.x + threadIdx.x;
    int node = t >> 5, lane = t & 31;
    if (node >= NN) return;
    float4 a = *(const float4*)&g_buf[(size_t)node * F + lane * 4];
    a.x = fmaxf(a.x, 0.f); a.y = fmaxf(a.y, 0.f);
    a.z = fmaxf(a.z, 0.f); a.w = fmaxf(a.w, 0.f);
    float4 w = *(const float4*)&Wf[lane * 4];
    float sum = a.x * w.x + a.y * w.y + a.z * w.z + a.w * w.w;
    #pragma unroll
    for (int o = 16; o; o >>= 1) sum += __shfl_xor_sync(0xffffffffu, sum, o);
    if (lane == 0) g_hf[node] = sum;
}

__global__ void k_fin_init(const float* __restrict__ bf, float* __restrict__ out) {
    int i = blockIdx.x * blockDim.x + threadIdx.x;
    if (i < NN) {
        float dv = g_dinv[i];
        out[i] = dv * dv * g_hf[i] + bf[0];
    }
}

__global__ void k_fin_scatter(const int* __restrict__ ei,
                              float* __restrict__ out) {
    int e = blockIdx.x * blockDim.x + threadIdx.x;
    if (e < NE) atomicAdd(&out[ei[NE + e]], g_enorm[e] * g_hf[ei[e]]);
}

// ------------------------------- launch ------------------------------------
extern "C" void kernel_launch(void* const* d_in, const int* in_sizes, int n_in,
                              void* d_out, int out_size) {
    const float* x   = (const float*)d_in[0];
    const int*   ei  = (const int*)d_in[1];
    const float* ew  = (const float*)d_in[2];
    const float* Win = (const float*)d_in[3];
    const float* bin = (const float*)d_in[4];
    const float* Wmd = (const float*)d_in[5];
    const float* bmd = (const float*)d_in[6];
    const float* Wfn = (const float*)d_in[7];
    const float* bfn = (const float*)d_in[8];
    float* out = (float*)d_out;

    const int TB = 256;
    const int gN  = (NN + TB - 1) / TB;          // 391
    const int gE  = (NE + TB - 1) / TB;          // 6250
    const int gEW = (NE * 32 + TB - 1) / TB;     // 200000 (warp/edge)
    const int gG  = (NN + 63) / 64;              // 1563
    const int gD  = (NN * 32 + TB - 1) / TB;     // 12500 (warp/node)

    // normalization
    k_deg_init<<<gN, TB>>>();
    k_deg_acc<<<gE, TB>>>(ei, ew);
    k_dinv<<<gN, TB>>>();
    k_enorm<<<gE, TB>>>(ei, ew);

    // layer 1: h = x @ W_in ; buf = agg + self*h + b ; (relu fused into next load)
    k_gemm<<<gG, TB>>>(x, Win, /*use_gbuf=*/0, /*relu_in=*/0);
    k_init<<<NN, F>>>(bin);
    k_scatter<<<gEW, TB>>>(ei);

    // layer 2: h = relu(buf) @ W_mid
    k_gemm<<<gG, TB>>>(nullptr, Wmd, 1, 1);
    k_init<<<NN, F>>>(bmd);
    k_scatter<<<gEW, TB>>>(ei);

    // layer 3: h = relu(buf) @ W_mid
    k_gemm<<<gG, TB>>>(nullptr, Wmd, 1, 1);
    k_init<<<NN, F>>>(bmd);
    k_scatter<<<gEW, TB>>>(ei);

    // final: hf = relu(buf) . W_fin ; out = agg + self*hf + b_fin
    k_dot<<<gD, TB>>>(Wfn);
    k_fin_init<<<gN, TB>>>(bfn, out);
    k_fin_scatter<<<gE, TB>>>(ei, out);
}

// round 3
// speedup vs baseline: 2.0549x; 2.0549x over previous
#include <cuda_runtime.h>

#define NN 100000
#define NE 1600000
#define F 128

// -------- scratch (static device globals; no allocations allowed) ----------
__device__ float g_dinv[NN];                 // deg -> deg^-1/2
__device__ int   g_deg[NN];                  // integer in-degree (dst)
__device__ int   g_rowptr[NN + 1];           // CSR row pointers (by dst)
__device__ int   g_cursor[NN];               // fill cursors
__device__ int   g_csr_src[NE];              // CSR: source node per edge
__device__ float g_csr_w[NE];                // CSR: normalized edge weight
__device__ float g_h[(size_t)NN * F];        // h = act(prev) @ W
__device__ float g_buf[(size_t)NN * F];      // layer output (agg + self + b)
__device__ float g_hf[NN];                   // final-layer per-node scalar

// ---------------------------- normalization --------------------------------
__global__ void k_deg_init() {
    int i = blockIdx.x * blockDim.x + threadIdx.x;
    if (i < NN) { g_dinv[i] = 1.0f; g_deg[i] = 0; }   // self-loop weight 1
}

__global__ void k_deg_acc(const int* __restrict__ ei,
                          const float* __restrict__ ew) {
    int e = blockIdx.x * blockDim.x + threadIdx.x;
    if (e < NE) {
        int d = ei[NE + e];
        atomicAdd(&g_dinv[d], ew[e]);
        atomicAdd(&g_deg[d], 1);
    }
}

__global__ void k_dinv() {
    int i = blockIdx.x * blockDim.x + threadIdx.x;
    if (i < NN) g_dinv[i] = rsqrtf(g_dinv[i]);   // deg >= 1 always
}

// single-block exclusive scan over g_deg -> g_rowptr (+ cursor copy)
__global__ __launch_bounds__(1024) void k_scan() {
    const int T = 1024;
    const int PER = (NN + T - 1) / T;            // 98
    __shared__ int tmp[T];
    int t = threadIdx.x;
    int start = t * PER;
    int end = start + PER; if (end > NN) end = NN;
    int sum = 0;
    for (int i = start; i < end; i++) sum += g_deg[i];
    tmp[t] = sum;
    __syncthreads();
    // Hillis-Steele inclusive scan
    for (int off = 1; off < T; off <<= 1) {
        int v = (t >= off) ? tmp[t - off] : 0;
        __syncthreads();
        tmp[t] += v;
        __syncthreads();
    }
    int run = tmp[t] - sum;                      // exclusive prefix
    for (int i = start; i < end; i++) {
        g_rowptr[i] = run;
        g_cursor[i] = run;
        run += g_deg[i];
    }
    if (end == NN && start < NN) g_rowptr[NN] = run;
}

// place each edge into CSR, computing its normalization on the fly
__global__ void k_fill(const int* __restrict__ ei,
                       const float* __restrict__ ew) {
    int e = blockIdx.x * blockDim.x + threadIdx.x;
    if (e >= NE) return;
    int s = ei[e], d = ei[NE + e];
    int pos = atomicAdd(&g_cursor[d], 1);
    g_csr_src[pos] = s;
    g_csr_w[pos] = g_dinv[s] * ew[e] * g_dinv[d];
}

// ------------------------------- GEMM ---------------------------------------
// g_h[NN,128] = act(A) @ W, act = relu if relu_in. A = (use_gbuf ? g_buf : Aext)
__global__ __launch_bounds__(256) void k_gemm(const float* __restrict__ Aext,
                                              const float* __restrict__ W,
                                              int use_gbuf, int relu_in) {
    const float* __restrict__ A = use_gbuf ? (const float*)g_buf : Aext;
    __shared__ float As[64][32];
    __shared__ float Ws[32][128];
    int tid = threadIdx.x;
    int tx = tid & 31;          // 32 column-groups of 4 cols
    int ty = tid >> 5;          // 8 row-groups of 8 rows
    int row0 = blockIdx.x * 64;
    float acc[8][4] = {};

    for (int kc = 0; kc < F; kc += 32) {
        #pragma unroll
        for (int i = 0; i < 2; i++) {
            int idx = tid + i * 256;
            int r = idx >> 3, c4 = idx & 7;
            int row = row0 + r;
            float4 v = make_float4(0.f, 0.f, 0.f, 0.f);
            if (row < NN) v = *(const float4*)&A[(size_t)row * F + kc + c4 * 4];
            if (relu_in) {
                v.x = fmaxf(v.x, 0.f); v.y = fmaxf(v.y, 0.f);
                v.z = fmaxf(v.z, 0.f); v.w = fmaxf(v.w, 0.f);
            }
            *(float4*)&As[r][c4 * 4] = v;
        }
        #pragma unroll
        for (int i = 0; i < 4; i++) {
            int idx = tid + i * 256;
            int k = idx >> 5, c4 = idx & 31;
            *(float4*)&Ws[k][c4 * 4] = *(const float4*)&W[(kc + k) * F + c4 * 4];
        }
        __syncthreads();
        #pragma unroll 8
        for (int k = 0; k < 32; k++) {
            float4 w4 = *(const float4*)&Ws[k][tx * 4];
            #pragma unroll
            for (int r = 0; r < 8; r++) {
                float a = As[ty * 8 + r][k];
                acc[r][0] += a * w4.x; acc[r][1] += a * w4.y;
                acc[r][2] += a * w4.z; acc[r][3] += a * w4.w;
            }
        }
        __syncthreads();
    }
    #pragma unroll
    for (int r = 0; r < 8; r++) {
        int row = row0 + ty * 8 + r;
        if (row < NN)
            *(float4*)&g_h[(size_t)row * F + tx * 4] =
                make_float4(acc[r][0], acc[r][1], acc[r][2], acc[r][3]);
    }
}

// ----------------------- aggregation: CSR gather ----------------------------
// buf[n,f] = dinv[n]^2 * h[n,f] + b[f] + sum_e w[e] * h[src[e], f]
__global__ __launch_bounds__(128) void k_gather(const float* __restrict__ b) {
    int node = blockIdx.x, f = threadIdx.x;
    float dv = g_dinv[node];
    float acc = dv * dv * g_h[(size_t)node * F + f] + b[f];
    int beg = g_rowptr[node], end = g_rowptr[node + 1];
    int e = beg;
    for (; e + 4 <= end; e += 4) {
        int s0 = g_csr_src[e],     s1 = g_csr_src[e + 1];
        int s2 = g_csr_src[e + 2], s3 = g_csr_src[e + 3];
        float w0 = g_csr_w[e],     w1 = g_csr_w[e + 1];
        float w2 = g_csr_w[e + 2], w3 = g_csr_w[e + 3];
        float h0 = g_h[(size_t)s0 * F + f];
        float h1 = g_h[(size_t)s1 * F + f];
        float h2 = g_h[(size_t)s2 * F + f];
        float h3 = g_h[(size_t)s3 * F + f];
        acc += w0 * h0; acc += w1 * h1; acc += w2 * h2; acc += w3 * h3;
    }
    for (; e < end; e++)
        acc += g_csr_w[e] * g_h[(size_t)g_csr_src[e] * F + f];
    g_buf[(size_t)node * F + f] = acc;
}

// ------------------------------ final layer --------------------------------
// g_hf[i] = relu(g_buf[i,:]) . W_fin   (warp per node)
__global__ void k_dot(const float* __restrict__ Wf) {
    int t = blockIdx.x * blockDim.x + threadIdx.x;
    int node = t >> 5, lane = t & 31;
    if (node >= NN) return;
    float4 a = *(const float4*)&g_buf[(size_t)node * F + lane * 4];
    a.x = fmaxf(a.x, 0.f); a.y = fmaxf(a.y, 0.f);
    a.z = fmaxf(a.z, 0.f); a.w = fmaxf(a.w, 0.f);
    float4 w = *(const float4*)&Wf[lane * 4];
    float sum = a.x * w.x + a.y * w.y + a.z * w.z + a.w * w.w;
    #pragma unroll
    for (int o = 16; o; o >>= 1) sum += __shfl_xor_sync(0xffffffffu, sum, o);
    if (lane == 0) g_hf[node] = sum;
}

// out[i] = dinv^2 * hf[i] + bf + sum_e w[e] * hf[src[e]]
__global__ void k_fin(const float* __restrict__ bf, float* __restrict__ out) {
    int i = blockIdx.x * blockDim.x + threadIdx.x;
    if (i >= NN) return;
    float dv = g_dinv[i];
    float acc = dv * dv * g_hf[i] + bf[0];
    int beg = g_rowptr[i], end = g_rowptr[i + 1];
    for (int e = beg; e < end; e++)
        acc += g_csr_w[e] * g_hf[g_csr_src[e]];
    out[i] = acc;
}

// ------------------------------- launch ------------------------------------
extern "C" void kernel_launch(void* const* d_in, const int* in_sizes, int n_in,
                              void* d_out, int out_size) {
    const float* x   = (const float*)d_in[0];
    const int*   ei  = (const int*)d_in[1];
    const float* ew  = (const float*)d_in[2];
    const float* Win = (const float*)d_in[3];
    const float* bin = (const float*)d_in[4];
    const float* Wmd = (const float*)d_in[5];
    const float* bmd = (const float*)d_in[6];
    const float* Wfn = (const float*)d_in[7];
    const float* bfn = (const float*)d_in[8];
    float* out = (float*)d_out;

    const int TB = 256;
    const int gN = (NN + TB - 1) / TB;           // 391
    const int gE = (NE + TB - 1) / TB;           // 6250
    const int gG = (NN + 63) / 64;               // 1563
    const int gD = (NN * 32 + TB - 1) / TB;      // 12500 (warp/node)

    // normalization + CSR build (once; reused by all 4 layers)
    k_deg_init<<<gN, TB>>>();
    k_deg_acc<<<gE, TB>>>(ei, ew);
    k_dinv<<<gN, TB>>>();
    k_scan<<<1, 1024>>>();
    k_fill<<<gE, TB>>>(ei, ew);

    // layer 1: h = x @ W_in ; buf = agg(h) + self*h + b
    k_gemm<<<gG, TB>>>(x, Win, 0, 0);
    k_gather<<<NN, F>>>(bin);

    // layer 2
    k_gemm<<<gG, TB>>>(nullptr, Wmd, 1, 1);
    k_gather<<<NN, F>>>(bmd);

    // layer 3
    k_gemm<<<gG, TB>>>(nullptr, Wmd, 1, 1);
    k_gather<<<NN, F>>>(bmd);

    // final layer
    k_dot<<<gD, TB>>>(Wfn);
    k_fin<<<gN, TB>>>(bfn, out);
}

// round 4
// speedup vs baseline: 2.2208x; 1.0808x over previous
#include <cuda_runtime.h>

#define NN 100000
#define NE 1600000
#define F 128
#define NBLK 98   // ceil(NN/1024)

// -------- scratch (static device globals; no allocations allowed) ----------
__device__ float g_dinv[NN];                 // deg -> deg^-1/2
__device__ int   g_deg[NN];                  // integer in-degree (dst)
__device__ int   g_part[NBLK];               // scan partials
__device__ int   g_rowptr[NN + 1];           // CSR row pointers (by dst)
__device__ int   g_cursor[NN];               // fill cursors
__device__ int   g_csr_src[NE];              // CSR: source node per edge
__device__ float g_csr_w[NE];                // CSR: normalized edge weight
__device__ float g_h[(size_t)NN * F];        // h = act(prev) @ W
__device__ float g_buf[(size_t)NN * F];      // layer output (agg + self + b)
__device__ float g_hf[NN];                   // final-layer per-node scalar

// ---------------------------- normalization --------------------------------
__global__ void k_deg_init() {
    int i = blockIdx.x * blockDim.x + threadIdx.x;
    if (i < NN) { g_dinv[i] = 1.0f; g_deg[i] = 0; }   // self-loop weight 1
}

__global__ void k_deg_acc(const int* __restrict__ ei,
                          const float* __restrict__ ew) {
    int e = blockIdx.x * blockDim.x + threadIdx.x;
    if (e < NE) {
        int d = ei[NE + e];
        atomicAdd(&g_dinv[d], ew[e]);
        atomicAdd(&g_deg[d], 1);
    }
}

__global__ void k_dinv() {
    int i = blockIdx.x * blockDim.x + threadIdx.x;
    if (i < NN) g_dinv[i] = rsqrtf(g_dinv[i]);   // deg >= 1 always
}

// --------------------- 3-phase parallel exclusive scan ----------------------
__global__ __launch_bounds__(1024) void k_scan1() {
    __shared__ int s[1024];
    int t = threadIdx.x, i = blockIdx.x * 1024 + t;
    s[t] = (i < NN) ? g_deg[i] : 0;
    __syncthreads();
    for (int off = 512; off; off >>= 1) {
        if (t < off) s[t] += s[t + off];
        __syncthreads();
    }
    if (t == 0) g_part[blockIdx.x] = s[0];
}

__global__ __launch_bounds__(128) void k_scan2() {
    __shared__ int s[128];
    int t = threadIdx.x;
    int v = (t < NBLK) ? g_part[t] : 0;
    s[t] = v;
    __syncthreads();
    for (int off = 1; off < 128; off <<= 1) {
        int u = (t >= off) ? s[t - off] : 0;
        __syncthreads();
        s[t] += u;
        __syncthreads();
    }
    if (t < NBLK) g_part[t] = s[t] - v;          // exclusive prefix of partials
    if (t == 127) g_rowptr[NN] = s[127];         // total edge count
}

__global__ __launch_bounds__(1024) void k_scan3() {
    __shared__ int s[1024];
    int t = threadIdx.x, i = blockIdx.x * 1024 + t;
    int v = (i < NN) ? g_deg[i] : 0;
    s[t] = v;
    __syncthreads();
    for (int off = 1; off < 1024; off <<= 1) {
        int u = (t >= off) ? s[t - off] : 0;
        __syncthreads();
        s[t] += u;
        __syncthreads();
    }
    if (i < NN) {
        int ex = s[t] - v + g_part[blockIdx.x];
        g_rowptr[i] = ex;
        g_cursor[i] = ex;
    }
}

// place each edge into CSR, computing its normalization on the fly
__global__ void k_fill(const int* __restrict__ ei,
                       const float* __restrict__ ew) {
    int e = blockIdx.x * blockDim.x + threadIdx.x;
    if (e >= NE) return;
    int s = ei[e], d = ei[NE + e];
    int pos = atomicAdd(&g_cursor[d], 1);
    g_csr_src[pos] = s;
    g_csr_w[pos] = g_dinv[s] * ew[e] * g_dinv[d];
}

// ------------------------------- GEMM ---------------------------------------
// 128x128 block tile, 256 threads, 8x8 micro-tile.
// g_h[NN,128] = act(A) @ W, act = relu if relu_in. A = (use_gbuf ? g_buf : Aext)
__global__ __launch_bounds__(256) void k_gemm(const float* __restrict__ Aext,
                                              const float* __restrict__ W,
                                              int use_gbuf, int relu_in) {
    const float* __restrict__ A = use_gbuf ? (const float*)g_buf : Aext;
    __shared__ float As[128][32];     // [row][k]
    __shared__ float Ws[32][128];     // [k][col]
    int tid = threadIdx.x;
    int tx = tid & 15;                // 16 col-groups of 8
    int ty = tid >> 4;                // 16 row-groups of 8
    int row0 = blockIdx.x * 128;
    float acc[8][8] = {};

    for (int kc = 0; kc < F; kc += 32) {
        // load A tile 128x32 = 1024 float4, 4/thread
        #pragma unroll
        for (int i = 0; i < 4; i++) {
            int idx = tid + i * 256;
            int r = idx >> 3, k4 = idx & 7;
            int row = row0 + r;
            float4 v = make_float4(0.f, 0.f, 0.f, 0.f);
            if (row < NN) v = *(const float4*)&A[(size_t)row * F + kc + k4 * 4];
            if (relu_in) {
                v.x = fmaxf(v.x, 0.f); v.y = fmaxf(v.y, 0.f);
                v.z = fmaxf(v.z, 0.f); v.w = fmaxf(v.w, 0.f);
            }
            *(float4*)&As[r][k4 * 4] = v;
        }
        // load W tile 32x128 = 1024 float4, 4/thread
        #pragma unroll
        for (int i = 0; i < 4; i++) {
            int idx = tid + i * 256;
            int k = idx >> 5, c4 = idx & 31;
            *(float4*)&Ws[k][c4 * 4] = *(const float4*)&W[(kc + k) * F + c4 * 4];
        }
        __syncthreads();
        #pragma unroll
        for (int k = 0; k < 32; k++) {
            float4 w0 = *(const float4*)&Ws[k][tx * 8];
            float4 w1 = *(const float4*)&Ws[k][tx * 8 + 4];
            float a[8];
            #pragma unroll
            for (int r = 0; r < 8; r++) a[r] = As[ty * 8 + r][k];
            #pragma unroll
            for (int r = 0; r < 8; r++) {
                acc[r][0] += a[r] * w0.x; acc[r][1] += a[r] * w0.y;
                acc[r][2] += a[r] * w0.z; acc[r][3] += a[r] * w0.w;
                acc[r][4] += a[r] * w1.x; acc[r][5] += a[r] * w1.y;
                acc[r][6] += a[r] * w1.z; acc[r][7] += a[r] * w1.w;
            }
        }
        __syncthreads();
    }
    #pragma unroll
    for (int r = 0; r < 8; r++) {
        int row = row0 + ty * 8 + r;
        if (row < NN) {
            *(float4*)&g_h[(size_t)row * F + tx * 8] =
                make_float4(acc[r][0], acc[r][1], acc[r][2], acc[r][3]);
            *(float4*)&g_h[(size_t)row * F + tx * 8 + 4] =
                make_float4(acc[r][4], acc[r][5], acc[r][6], acc[r][7]);
        }
    }
}

// ----------------------- aggregation: CSR gather ----------------------------
// buf[n,f] = dinv[n]^2 * h[n,f] + b[f] + sum_e w[e] * h[src[e], f]
__global__ __launch_bounds__(128) void k_gather(const float* __restrict__ b) {
    int node = blockIdx.x, f = threadIdx.x;
    float dv = g_dinv[node];
    float acc = dv * dv * g_h[(size_t)node * F + f] + b[f];
    int beg = g_rowptr[node], end = g_rowptr[node + 1];
    int e = beg;
    for (; e + 4 <= end; e += 4) {
        int s0 = g_csr_src[e],     s1 = g_csr_src[e + 1];
        int s2 = g_csr_src[e + 2], s3 = g_csr_src[e + 3];
        float w0 = g_csr_w[e],     w1 = g_csr_w[e + 1];
        float w2 = g_csr_w[e + 2], w3 = g_csr_w[e + 3];
        float h0 = g_h[(size_t)s0 * F + f];
        float h1 = g_h[(size_t)s1 * F + f];
        float h2 = g_h[(size_t)s2 * F + f];
        float h3 = g_h[(size_t)s3 * F + f];
        acc += w0 * h0; acc += w1 * h1; acc += w2 * h2; acc += w3 * h3;
    }
    for (; e < end; e++)
        acc += g_csr_w[e] * g_h[(size_t)g_csr_src[e] * F + f];
    g_buf[(size_t)node * F + f] = acc;
}

// ------------------------------ final layer --------------------------------
// g_hf[i] = relu(g_buf[i,:]) . W_fin   (warp per node)
__global__ void k_dot(const float* __restrict__ Wf) {
    int t = blockIdx.x * blockDim.x + threadIdx.x;
    int node = t >> 5, lane = t & 31;
    if (node >= NN) return;
    float4 a = *(const float4*)&g_buf[(size_t)node * F + lane * 4];
    a.x = fmaxf(a.x, 0.f); a.y = fmaxf(a.y, 0.f);
    a.z = fmaxf(a.z, 0.f); a.w = fmaxf(a.w, 0.f);
    float4 w = *(const float4*)&Wf[lane * 4];
    float sum = a.x * w.x + a.y * w.y + a.z * w.z + a.w * w.w;
    #pragma unroll
    for (int o = 16; o; o >>= 1) sum += __shfl_xor_sync(0xffffffffu, sum, o);
    if (lane == 0) g_hf[node] = sum;
}

// out[i] = dinv^2 * hf[i] + bf + sum_e w[e] * hf[src[e]]
__global__ void k_fin(const float* __restrict__ bf, float* __restrict__ out) {
    int i = blockIdx.x * blockDim.x + threadIdx.x;
    if (i >= NN) return;
    float dv = g_dinv[i];
    float acc = dv * dv * g_hf[i] + bf[0];
    int beg = g_rowptr[i], end = g_rowptr[i + 1];
    for (int e = beg; e < end; e++)
        acc += g_csr_w[e] * g_hf[g_csr_src[e]];
    out[i] = acc;
}

// ------------------------------- launch ------------------------------------
extern "C" void kernel_launch(void* const* d_in, const int* in_sizes, int n_in,
                              void* d_out, int out_size) {
    const float* x   = (const float*)d_in[0];
    const int*   ei  = (const int*)d_in[1];
    const float* ew  = (const float*)d_in[2];
    const float* Win = (const float*)d_in[3];
    const float* bin = (const float*)d_in[4];
    const float* Wmd = (const float*)d_in[5];
    const float* bmd = (const float*)d_in[6];
    const float* Wfn = (const float*)d_in[7];
    const float* bfn = (const float*)d_in[8];
    float* out = (float*)d_out;

    const int TB = 256;
    const int gN = (NN + TB - 1) / TB;           // 391
    const int gE = (NE + TB - 1) / TB;           // 6250
    const int gG = (NN + 127) / 128;             // 782
    const int gD = (NN * 32 + TB - 1) / TB;      // 12500 (warp/node)

    // normalization + CSR build (once; reused by all 4 layers)
    k_deg_init<<<gN, TB>>>();
    k_deg_acc<<<gE, TB>>>(ei, ew);
    k_dinv<<<gN, TB>>>();
    k_scan1<<<NBLK, 1024>>>();
    k_scan2<<<1, 128>>>();
    k_scan3<<<NBLK, 1024>>>();
    k_fill<<<gE, TB>>>(ei, ew);

    // layer 1: h = x @ W_in ; buf = agg(h) + self*h + b
    k_gemm<<<gG, TB>>>(x, Win, 0, 0);
    k_gather<<<NN, F>>>(bin);

    // layer 2
    k_gemm<<<gG, TB>>>(nullptr, Wmd, 1, 1);
    k_gather<<<NN, F>>>(bmd);

    // layer 3
    k_gemm<<<gG, TB>>>(nullptr, Wmd, 1, 1);
    k_gather<<<NN, F>>>(bmd);

    // final layer
    k_dot<<<gD, TB>>>(Wfn);
    k_fin<<<gN, TB>>>(bfn, out);
}

// round 6
// speedup vs baseline: 2.7833x; 1.2533x over previous
#include <cuda_runtime.h>

#define NN 100000
#define NE 1600000
#define F 128
#define NBLK 98   // ceil(NN/1024)

// -------- scratch (static device globals; no allocations allowed) ----------
__device__ float g_dinv[NN];                 // deg -> deg^-1/2
__device__ int   g_deg[NN];                  // integer in-degree (dst)
__device__ int   g_part[NBLK];               // scan partials
__device__ int   g_rowptr[NN + 1];           // CSR row pointers (by dst)
__device__ int   g_cursor[NN];               // fill cursors
__device__ __align__(16) int2 g_csr[NE];     // CSR: (src, w-as-int) per edge
__device__ float g_h[(size_t)NN * F];        // h = act(prev) @ W
__device__ float g_buf[(size_t)NN * F];      // layer output (agg + self + b)
__device__ float g_hf[NN];                   // final-layer per-node scalar

// ---------------------------- normalization --------------------------------
__global__ void k_deg_init() {
    int i = blockIdx.x * blockDim.x + threadIdx.x;
    if (i < NN) { g_dinv[i] = 1.0f; g_deg[i] = 0; }   // self-loop weight 1
}

__global__ void k_deg_acc(const int* __restrict__ ei,
                          const float* __restrict__ ew) {
    int e = blockIdx.x * blockDim.x + threadIdx.x;
    if (e < NE) {
        int d = ei[NE + e];
        atomicAdd(&g_dinv[d], ew[e]);
        atomicAdd(&g_deg[d], 1);
    }
}

// --------------------- 3-phase parallel exclusive scan ----------------------
// phase 1 also finishes dinv (rsqrt), fusing the old k_dinv launch.
__global__ __launch_bounds__(1024) void k_scan1() {
    __shared__ int s[1024];
    int t = threadIdx.x, i = blockIdx.x * 1024 + t;
    if (i < NN) g_dinv[i] = rsqrtf(g_dinv[i]);   // deg >= 1 always
    s[t] = (i < NN) ? g_deg[i] : 0;
    __syncthreads();
    for (int off = 512; off; off >>= 1) {
        if (t < off) s[t] += s[t + off];
        __syncthreads();
    }
    if (t == 0) g_part[blockIdx.x] = s[0];
}

__global__ __launch_bounds__(128) void k_scan2() {
    __shared__ int s[128];
    int t = threadIdx.x;
    int v = (t < NBLK) ? g_part[t] : 0;
    s[t] = v;
    __syncthreads();
    for (int off = 1; off < 128; off <<= 1) {
        int u = (t >= off) ? s[t - off] : 0;
        __syncthreads();
        s[t] += u;
        __syncthreads();
    }
    if (t < NBLK) g_part[t] = s[t] - v;          // exclusive prefix of partials
    if (t == 127) g_rowptr[NN] = s[127];         // total edge count
}

__global__ __launch_bounds__(1024) void k_scan3() {
    __shared__ int s[1024];
    int t = threadIdx.x, i = blockIdx.x * 1024 + t;
    int v = (i < NN) ? g_deg[i] : 0;
    s[t] = v;
    __syncthreads();
    for (int off = 1; off < 1024; off <<= 1) {
        int u = (t >= off) ? s[t - off] : 0;
        __syncthreads();
        s[t] += u;
        __syncthreads();
    }
    if (i < NN) {
        int ex = s[t] - v + g_part[blockIdx.x];
        g_rowptr[i] = ex;
        g_cursor[i] = ex;
    }
}

// place each edge into CSR, computing its normalization on the fly
__global__ void k_fill(const int* __restrict__ ei,
                       const float* __restrict__ ew) {
    int e = blockIdx.x * blockDim.x + threadIdx.x;
    if (e >= NE) return;
    int s = ei[e], d = ei[NE + e];
    int pos = atomicAdd(&g_cursor[d], 1);
    float w = g_dinv[s] * ew[e] * g_dinv[d];
    g_csr[pos] = make_int2(s, __float_as_int(w));
}

// ------------------------------- GEMM ---------------------------------------
// 128x128 block tile, 256 threads, 8x8 micro-tile (FFMA-rt bound).
__global__ __launch_bounds__(256) void k_gemm(const float* __restrict__ Aext,
                                              const float* __restrict__ W,
                                              int use_gbuf, int relu_in) {
    const float* __restrict__ A = use_gbuf ? (const float*)g_buf : Aext;
    __shared__ float As[128][32];     // [row][k]
    __shared__ float Ws[32][128];     // [k][col]
    int tid = threadIdx.x;
    int tx = tid & 15;                // 16 col-groups of 8
    int ty = tid >> 4;                // 16 row-groups of 8
    int row0 = blockIdx.x * 128;
    float acc[8][8] = {};

    for (int kc = 0; kc < F; kc += 32) {
        #pragma unroll
        for (int i = 0; i < 4; i++) {
            int idx = tid + i * 256;
            int r = idx >> 3, k4 = idx & 7;
            int row = row0 + r;
            float4 v = make_float4(0.f, 0.f, 0.f, 0.f);
            if (row < NN) v = *(const float4*)&A[(size_t)row * F + kc + k4 * 4];
            if (relu_in) {
                v.x = fmaxf(v.x, 0.f); v.y = fmaxf(v.y, 0.f);
                v.z = fmaxf(v.z, 0.f); v.w = fmaxf(v.w, 0.f);
            }
            *(float4*)&As[r][k4 * 4] = v;
        }
        #pragma unroll
        for (int i = 0; i < 4; i++) {
            int idx = tid + i * 256;
            int k = idx >> 5, c4 = idx & 31;
            *(float4*)&Ws[k][c4 * 4] = *(const float4*)&W[(kc + k) * F + c4 * 4];
        }
        __syncthreads();
        #pragma unroll
        for (int k = 0; k < 32; k++) {
            float4 w0 = *(const float4*)&Ws[k][tx * 8];
            float4 w1 = *(const float4*)&Ws[k][tx * 8 + 4];
            float a[8];
            #pragma unroll
            for (int r = 0; r < 8; r++) a[r] = As[ty * 8 + r][k];
            #pragma unroll
            for (int r = 0; r < 8; r++) {
                acc[r][0] += a[r] * w0.x; acc[r][1] += a[r] * w0.y;
                acc[r][2] += a[r] * w0.z; acc[r][3] += a[r] * w0.w;
                acc[r][4] += a[r] * w1.x; acc[r][5] += a[r] * w1.y;
                acc[r][6] += a[r] * w1.z; acc[r][7] += a[r] * w1.w;
            }
        }
        __syncthreads();
    }
    #pragma unroll
    for (int r = 0; r < 8; r++) {
        int row = row0 + ty * 8 + r;
        if (row < NN) {
            *(float4*)&g_h[(size_t)row * F + tx * 8] =
                make_float4(acc[r][0], acc[r][1], acc[r][2], acc[r][3]);
            *(float4*)&g_h[(size_t)row * F + tx * 8 + 4] =
                make_float4(acc[r][4], acc[r][5], acc[r][6], acc[r][7]);
        }
    }
}

// ----------------------- aggregation: CSR gather ----------------------------
// Warp per node, float4 per lane (lane covers features lane*4..lane*4+3).
// buf[n,:] = dinv^2 * h[n,:] + b + sum_e w[e] * h[src[e],:]
// If do_dot: instead emit g_hf[n] = relu(row) . Wf  (fuses the final k_dot).
__global__ __launch_bounds__(256) void k_gather(const float* __restrict__ b,
                                                int do_dot,
                                                const float* __restrict__ Wf) {
    int node = blockIdx.x * 8 + (threadIdx.x >> 5);
    int lane = threadIdx.x & 31;
    if (node >= NN) return;
    const float4* __restrict__ h4 = (const float4*)g_h;

    float dv = g_dinv[node];
    float4 hv = h4[(size_t)node * 32 + lane];
    float s2 = dv * dv;
    float4 acc;
    float4 bv = *(const float4*)&b[lane * 4];
    acc.x = s2 * hv.x + bv.x; acc.y = s2 * hv.y + bv.y;
    acc.z = s2 * hv.z + bv.z; acc.w = s2 * hv.w + bv.w;

    int beg = g_rowptr[node], end = g_rowptr[node + 1];
    int e = beg;
    // peel to even index so int4 loads below are 16B-aligned
    if ((e & 1) && e < end) {
        int2 p = g_csr[e];
        float w = __int_as_float(p.y);
        float4 v = h4[(size_t)p.x * 32 + lane];
        acc.x += w * v.x; acc.y += w * v.y;
        acc.z += w * v.z; acc.w += w * v.w;
        e++;
    }
    for (; e + 2 <= end; e += 2) {
        int4 p = *(const int4*)&g_csr[e];         // two (src,w) pairs, aligned
        float w0 = __int_as_float(p.y);
        float w1 = __int_as_float(p.w);
        float4 v0 = h4[(size_t)p.x * 32 + lane];
        float4 v1 = h4[(size_t)p.z * 32 + lane];
        acc.x += w0 * v0.x; acc.y += w0 * v0.y;
        acc.z += w0 * v0.z; acc.w += w0 * v0.w;
        acc.x += w1 * v1.x; acc.y += w1 * v1.y;
        acc.z += w1 * v1.z; acc.w += w1 * v1.w;
    }
    if (e < end) {
        int2 p = g_csr[e];
        float w = __int_as_float(p.y);
        float4 v = h4[(size_t)p.x * 32 + lane];
        acc.x += w * v.x; acc.y += w * v.y;
        acc.z += w * v.z; acc.w += w * v.w;
    }

    if (!do_dot) {
        ((float4*)g_buf)[(size_t)node * 32 + lane] = acc;
    } else {
        acc.x = fmaxf(acc.x, 0.f); acc.y = fmaxf(acc.y, 0.f);
        acc.z = fmaxf(acc.z, 0.f); acc.w = fmaxf(acc.w, 0.f);
        float4 wf = *(const float4*)&Wf[lane * 4];
        float sum = acc.x * wf.x + acc.y * wf.y + acc.z * wf.z + acc.w * wf.w;
        #pragma unroll
        for (int o = 16; o; o >>= 1) sum += __shfl_xor_sync(0xffffffffu, sum, o);
        if (lane == 0) g_hf[node] = sum;
    }
}

// ------------------------------ final layer --------------------------------
// out[i] = dinv^2 * hf[i] + bf + sum_e w[e] * hf[src[e]]
__global__ void k_fin(const float* __restrict__ bf, float* __restrict__ out) {
    int i = blockIdx.x * blockDim.x + threadIdx.x;
    if (i >= NN) return;
    float dv = g_dinv[i];
    float acc = dv * dv * g_hf[i] + bf[0];
    int beg = g_rowptr[i], end = g_rowptr[i + 1];
    for (int e = beg; e < end; e++) {
        int2 p = g_csr[e];
        acc += __int_as_float(p.y) * g_hf[p.x];
    }
    out[i] = acc;
}

// ------------------------------- launch ------------------------------------
extern "C" void kernel_launch(void* const* d_in, const int* in_sizes, int n_in,
                              void* d_out, int out_size) {
    const float* x   = (const float*)d_in[0];
    const int*   ei  = (const int*)d_in[1];
    const float* ew  = (const float*)d_in[2];
    const float* Win = (const float*)d_in[3];
    const float* bin = (const float*)d_in[4];
    const float* Wmd = (const float*)d_in[5];
    const float* bmd = (const float*)d_in[6];
    const float* Wfn = (const float*)d_in[7];
    const float* bfn = (const float*)d_in[8];
    float* out = (float*)d_out;

    const int TB = 256;
    const int gN = (NN + TB - 1) / TB;           // 391
    const int gE = (NE + TB - 1) / TB;           // 6250
    const int gG = (NN + 127) / 128;             // 782
    const int gA = (NN + 7) / 8;                 // 12500 (warp/node)

    // CSR build; gemm1 is graph-independent, placed at launch #5 so the
    // ncu capture (-s 5 -c 1) lands on the hot GEMM.
    k_deg_init<<<gN, TB>>>();                    // 0
    k_deg_acc<<<gE, TB>>>(ei, ew);               // 1
    k_scan1<<<NBLK, 1024>>>();                   // 2 (also rsqrt)
    k_scan2<<<1, 128>>>();                       // 3
    k_scan3<<<NBLK, 1024>>>();                   // 4
    k_gemm<<<gG, TB>>>(x, Win, 0, 0);            // 5  <-- profiled
    k_fill<<<gE, TB>>>(ei, ew);                  // 6

    // layer 1 aggregate
    k_gather<<<gA, TB>>>(bin, 0, nullptr);

    // layer 2
    k_gemm<<<gG, TB>>>(nullptr, Wmd, 1, 1);
    k_gather<<<gA, TB>>>(bmd, 0, nullptr);

    // layer 3 (+ fused final dot)
    k_gemm<<<gG, TB>>>(nullptr, Wmd, 1, 1);
    k_gather<<<gA, TB>>>(bmd, 1, Wfn);

    // final aggregation (scalar)
    k_fin<<<gN, TB>>>(bfn, out);
}